// round 1
// baseline (speedup 1.0000x reference)
#include <cuda_runtime.h>
#include <math.h>

#define T_STEPS 1000
#define I_DIM   100
#define H_DIM   5000
#define O_DIM   100
#define ALPHA_F 0.1f
#define NOISE_F 0.1f

#define NBLK 148      // persistent grid: one CTA per SM (all co-resident)
#define NTH  512      // threads per CTA
#define NWARP (NTH/32)
#define MAXR 34       // max rows per CTA: ceil-split of 5000 over 148

// Scratch: injection buffer (T x H) and the grid barrier counter.
__device__ float    g_inj[(size_t)T_STEPS * H_DIM];
__device__ unsigned g_bar;

// ---------------------------------------------------------------------------
// Reset the barrier counter (must run before scan_k on every launch so the
// kernel sequence is deterministic across graph replays).
// ---------------------------------------------------------------------------
__global__ void reset_k() { g_bar = 0u; }

// ---------------------------------------------------------------------------
// inj[t][h] = sum_i u[t][i] * W_in[h][i] + 0.1 * noise[t][h]
// grid: (ceil(H/256), T), block: 256
// ---------------------------------------------------------------------------
__global__ void inj_k(const float* __restrict__ u,
                      const float* __restrict__ noise,
                      const float* __restrict__ W_in) {
    __shared__ float u_s[I_DIM];
    const int t   = blockIdx.y;
    const int tid = threadIdx.x;
    if (tid < I_DIM) u_s[tid] = u[(size_t)t * I_DIM + tid];
    __syncthreads();

    const int h = blockIdx.x * blockDim.x + tid;
    if (h < H_DIM) {
        const float4* w4 = reinterpret_cast<const float4*>(W_in + (size_t)h * I_DIM);
        float acc = 0.0f;
#pragma unroll
        for (int i = 0; i < I_DIM / 4; i++) {
            float4 w = __ldg(&w4[i]);
            acc = fmaf(w.x, u_s[4*i+0], acc);
            acc = fmaf(w.y, u_s[4*i+1], acc);
            acc = fmaf(w.z, u_s[4*i+2], acc);
            acc = fmaf(w.w, u_s[4*i+3], acc);
        }
        g_inj[(size_t)t * H_DIM + h] = acc + NOISE_F * noise[(size_t)t * H_DIM + h];
    }
}

// ---------------------------------------------------------------------------
// Persistent scan kernel: 1000 steps of
//   x = 0.9*x + 0.1*(W_rec @ r + inj_t);  r = tanh(x);  hs[t+1] = r
// hs[t] doubles as the r_t buffer. Grid-wide barrier per step.
// ---------------------------------------------------------------------------
__global__ void __launch_bounds__(NTH)
scan_k(const float* __restrict__ W,
       const float* __restrict__ r_in,
       float* __restrict__ hs) {
    __shared__ float r_s[H_DIM];             // 20 KB: current r vector
    __shared__ float x_s[MAXR];              // per-CTA x state
    __shared__ float part[NWARP][MAXR];      // cross-warp reduction scratch

    const int tid  = threadIdx.x;
    const int bid  = blockIdx.x;
    const int wid  = tid >> 5;
    const int lane = tid & 31;

    const int row0  = (int)(((long long)bid     * H_DIM) / NBLK);
    const int row1  = (int)(((long long)(bid+1) * H_DIM) / NBLK);
    const int nrows = row1 - row0;           // 33 or 34

    // hs[0] = r_in ; x0 = atanh(r_in) for this CTA's rows
    if (tid < nrows) {
        float rv = r_in[row0 + tid];
        hs[row0 + tid] = rv;
        x_s[tid] = atanhf(rv);
    }
    __syncthreads();

    const float* wbase = W + (size_t)row0 * H_DIM;

    for (int t = 0; t < T_STEPS; t++) {
        // Load r_t into shared (for t==0 straight from the input vector,
        // avoiding a pre-loop grid sync on hs[0]).
        const float* rsrc = (t == 0) ? r_in : (hs + (size_t)t * H_DIM);
        for (int c = tid; c < H_DIM; c += NTH) r_s[c] = __ldcg(rsrc + c);
        __syncthreads();

        // Partial dot products: columns strided over threads, MAXR row accs.
        float acc[MAXR];
#pragma unroll
        for (int rr = 0; rr < MAXR; rr++) acc[rr] = 0.0f;

        for (int c = tid; c < H_DIM; c += NTH) {
            const float rv  = r_s[c];
            const float* wp = wbase + c;
#pragma unroll
            for (int rr = 0; rr < MAXR; rr++) {
                if (rr < nrows)
                    acc[rr] = fmaf(__ldcg(wp + (size_t)rr * H_DIM), rv, acc[rr]);
            }
        }

        // Warp-level reduce each row accumulator, stash per-warp partials.
#pragma unroll
        for (int rr = 0; rr < MAXR; rr++) {
            float v = acc[rr];
            v += __shfl_down_sync(0xffffffffu, v, 16);
            v += __shfl_down_sync(0xffffffffu, v, 8);
            v += __shfl_down_sync(0xffffffffu, v, 4);
            v += __shfl_down_sync(0xffffffffu, v, 2);
            v += __shfl_down_sync(0xffffffffu, v, 1);
            if (lane == 0) part[wid][rr] = v;
        }
        __syncthreads();

        // Final cross-warp sum + state update (one thread per owned row).
        if (tid < nrows) {
            float s = 0.0f;
#pragma unroll
            for (int w = 0; w < NWARP; w++) s += part[w][tid];
            float x = (1.0f - ALPHA_F) * x_s[tid]
                    + ALPHA_F * (s + g_inj[(size_t)t * H_DIM + row0 + tid]);
            x_s[tid] = x;
            hs[(size_t)(t + 1) * H_DIM + row0 + tid] = tanhf(x);
        }
        __syncthreads();   // part[][] / x_s stable before next step; stores issued

        // Grid-wide barrier: release (fence+arrive) / spin / acquire (fence).
        if (tid == 0) {
            __threadfence();
            atomicAdd(&g_bar, 1u);
            const unsigned target = (unsigned)(t + 1) * (unsigned)NBLK;
            while (atomicAdd(&g_bar, 0u) < target) { }
            __threadfence();
        }
        __syncthreads();
    }
}

// ---------------------------------------------------------------------------
// o[t][j] = sum_h hs[t+1][h] * W_out[j][h]
// grid: T, block: 256 (8 warps; warp-per-output-row)
// ---------------------------------------------------------------------------
__global__ void out_k(const float* __restrict__ hs,
                      const float* __restrict__ W_out,
                      float* __restrict__ o) {
    __shared__ float r_s[H_DIM];
    const int t    = blockIdx.x;
    const int tid  = threadIdx.x;
    const int wid  = tid >> 5;
    const int lane = tid & 31;

    const float* r = hs + (size_t)(t + 1) * H_DIM;
    for (int c = tid; c < H_DIM; c += blockDim.x) r_s[c] = r[c];
    __syncthreads();

    for (int j = wid; j < O_DIM; j += blockDim.x / 32) {
        const float* wrow = W_out + (size_t)j * H_DIM;
        float acc = 0.0f;
        for (int c = lane; c < H_DIM; c += 32)
            acc = fmaf(__ldg(wrow + c), r_s[c], acc);
#pragma unroll
        for (int s = 16; s; s >>= 1) acc += __shfl_down_sync(0xffffffffu, acc, s);
        if (lane == 0) o[(size_t)t * O_DIM + j] = acc;
    }
}

// ---------------------------------------------------------------------------
// Inputs (metadata order): u (T,I), r (H), noise (T,H), W_in (H,I),
// W_rec (H,H), W_out (O,H).
// Output: hidden_states (T+1,H) followed by o (T,O), fp32.
// ---------------------------------------------------------------------------
extern "C" void kernel_launch(void* const* d_in, const int* in_sizes, int n_in,
                              void* d_out, int out_size) {
    const float* u     = (const float*)d_in[0];
    const float* r     = (const float*)d_in[1];
    const float* noise = (const float*)d_in[2];
    const float* W_in  = (const float*)d_in[3];
    const float* W_rec = (const float*)d_in[4];
    const float* W_out = (const float*)d_in[5];

    float* hs = (float*)d_out;                                  // (T+1, H)
    float* o  = hs + (size_t)(T_STEPS + 1) * H_DIM;             // (T, O)

    reset_k<<<1, 1>>>();
    dim3 gi((H_DIM + 255) / 256, T_STEPS);
    inj_k<<<gi, 256>>>(u, noise, W_in);
    scan_k<<<NBLK, NTH>>>(W_rec, r, hs);
    out_k<<<T_STEPS, 256>>>(hs, W_out, o);
}

// round 2
// speedup vs baseline: 1.6452x; 1.6452x over previous
#include <cuda_runtime.h>
#include <math.h>

#define T_STEPS 1000
#define I_DIM   100
#define H_DIM   5000
#define H4      (H_DIM/4)          // 1250 float4 per row
#define O_DIM   100
#define ALPHA_F 0.1f
#define NOISE_F 0.1f

#define NBLK  148      // persistent grid: one CTA per SM (all co-resident)
#define NTH   512
#define NWARP (NTH/32)
#define MAXR  34       // max rows per CTA

__device__ float    g_inj[(size_t)T_STEPS * H_DIM];
__device__ unsigned g_bar;

__global__ void reset_k() { g_bar = 0u; }
__global__ void nop_k() {}

// ---------------------------------------------------------------------------
// inj[t][h] = sum_i u[t][i] * W_in[h][i] + 0.1 * noise[t][h]
// ---------------------------------------------------------------------------
__global__ void inj_k(const float* __restrict__ u,
                      const float* __restrict__ noise,
                      const float* __restrict__ W_in) {
    __shared__ float u_s[I_DIM];
    const int t   = blockIdx.y;
    const int tid = threadIdx.x;
    if (tid < I_DIM) u_s[tid] = u[(size_t)t * I_DIM + tid];
    __syncthreads();

    const int h = blockIdx.x * blockDim.x + tid;
    if (h < H_DIM) {
        const float4* w4 = reinterpret_cast<const float4*>(W_in + (size_t)h * I_DIM);
        float acc = 0.0f;
#pragma unroll
        for (int i = 0; i < I_DIM / 4; i++) {
            float4 w = __ldg(&w4[i]);
            acc = fmaf(w.x, u_s[4*i+0], acc);
            acc = fmaf(w.y, u_s[4*i+1], acc);
            acc = fmaf(w.z, u_s[4*i+2], acc);
            acc = fmaf(w.w, u_s[4*i+3], acc);
        }
        g_inj[(size_t)t * H_DIM + h] = acc + NOISE_F * noise[(size_t)t * H_DIM + h];
    }
}

// ---------------------------------------------------------------------------
// Persistent scan: warp-per-row, float4 loads, volatile-poll grid barrier.
// ---------------------------------------------------------------------------
__global__ void __launch_bounds__(NTH)
scan_k(const float* __restrict__ W,
       const float* __restrict__ r_in,
       float* __restrict__ hs) {
    __shared__ float4 r_s4[H4];      // 20 KB: current r vector
    __shared__ float  x_s[MAXR];     // per-row membrane state

    const int tid  = threadIdx.x;
    const int bid  = blockIdx.x;
    const int wid  = tid >> 5;
    const int lane = tid & 31;

    const int row0  = (int)(((long long)bid     * H_DIM) / NBLK);
    const int row1  = (int)(((long long)(bid+1) * H_DIM) / NBLK);
    const int nrows = row1 - row0;   // 33 or 34

    if (tid < nrows) {
        float rv = r_in[row0 + tid];
        hs[row0 + tid] = rv;         // hidden_states[0]
        x_s[tid] = atanhf(rv);
    }
    __syncthreads();

    for (int t = 0; t < T_STEPS; t++) {
        // Stage r_t into shared (vectorized; .cg so L1 stays out of the way).
        const float4* rsrc = (t == 0)
            ? reinterpret_cast<const float4*>(r_in)
            : reinterpret_cast<const float4*>(hs + (size_t)t * H_DIM);
        for (int i = tid; i < H4; i += NTH) r_s4[i] = __ldcg(rsrc + i);
        __syncthreads();

        // Each warp owns rows wid, wid+16, wid+32 (local).
        for (int lr = wid; lr < nrows; lr += NWARP) {
            const int row = row0 + lr;
            const float4* wrow =
                reinterpret_cast<const float4*>(W + (size_t)row * H_DIM);

            // Prefetch injection early (consumed after the reduction).
            float injv = 0.0f;
            if (lane == 0) injv = __ldcg(&g_inj[(size_t)t * H_DIM + row]);

            float4 a = make_float4(0.f, 0.f, 0.f, 0.f);
#pragma unroll 5
            for (int i = lane; i < H4; i += 32) {
                float4 w  = __ldcg(wrow + i);
                float4 rv = r_s4[i];
                a.x = fmaf(w.x, rv.x, a.x);
                a.y = fmaf(w.y, rv.y, a.y);
                a.z = fmaf(w.z, rv.z, a.z);
                a.w = fmaf(w.w, rv.w, a.w);
            }
            float s = (a.x + a.y) + (a.z + a.w);
            s += __shfl_down_sync(0xffffffffu, s, 16);
            s += __shfl_down_sync(0xffffffffu, s, 8);
            s += __shfl_down_sync(0xffffffffu, s, 4);
            s += __shfl_down_sync(0xffffffffu, s, 2);
            s += __shfl_down_sync(0xffffffffu, s, 1);

            if (lane == 0) {
                float x = (1.0f - ALPHA_F) * x_s[lr] + ALPHA_F * (s + injv);
                x_s[lr] = x;
                hs[(size_t)(t + 1) * H_DIM + row] = tanhf(x);
            }
        }
        // Release: each storing lane fences its own stores, then CTA bar,
        // then leader arrives.
        if (lane == 0 && wid < nrows) __threadfence();
        __syncthreads();

        if (tid == 0) {
            atomicAdd(&g_bar, 1u);
            const unsigned target = (unsigned)(t + 1) * (unsigned)NBLK;
            while (*((volatile unsigned*)&g_bar) < target) { }
            __threadfence();   // acquire
        }
        __syncthreads();
    }
}

// ---------------------------------------------------------------------------
// o[t][j] = sum_h hs[t+1][h] * W_out[j][h]
// ---------------------------------------------------------------------------
__global__ void out_k(const float* __restrict__ hs,
                      const float* __restrict__ W_out,
                      float* __restrict__ o) {
    __shared__ float r_s[H_DIM];
    const int t    = blockIdx.x;
    const int tid  = threadIdx.x;
    const int wid  = tid >> 5;
    const int lane = tid & 31;

    const float* r = hs + (size_t)(t + 1) * H_DIM;
    for (int c = tid; c < H_DIM; c += blockDim.x) r_s[c] = r[c];
    __syncthreads();

    for (int j = wid; j < O_DIM; j += blockDim.x / 32) {
        const float* wrow = W_out + (size_t)j * H_DIM;
        float acc = 0.0f;
        for (int c = lane; c < H_DIM; c += 32)
            acc = fmaf(__ldg(wrow + c), r_s[c], acc);
#pragma unroll
        for (int s = 16; s; s >>= 1) acc += __shfl_down_sync(0xffffffffu, acc, s);
        if (lane == 0) o[(size_t)t * O_DIM + j] = acc;
    }
}

// ---------------------------------------------------------------------------
// Inputs: u (T,I), r (H), noise (T,H), W_in (H,I), W_rec (H,H), W_out (O,H).
// Output: hidden_states (T+1,H) then o (T,O), fp32.
// ---------------------------------------------------------------------------
extern "C" void kernel_launch(void* const* d_in, const int* in_sizes, int n_in,
                              void* d_out, int out_size) {
    const float* u     = (const float*)d_in[0];
    const float* r     = (const float*)d_in[1];
    const float* noise = (const float*)d_in[2];
    const float* W_in  = (const float*)d_in[3];
    const float* W_rec = (const float*)d_in[4];
    const float* W_out = (const float*)d_in[5];

    float* hs = (float*)d_out;                       // (T+1, H)
    float* o  = hs + (size_t)(T_STEPS + 1) * H_DIM;  // (T, O)

    reset_k<<<1, 1>>>();
    dim3 gi((H_DIM + 255) / 256, T_STEPS);
    inj_k<<<gi, 256>>>(u, noise, W_in);
    nop_k<<<1, 1>>>();   // shifts scan_k onto the ncu capture slot
    scan_k<<<NBLK, NTH>>>(W_rec, r, hs);
    out_k<<<T_STEPS, 256>>>(hs, W_out, o);
}

// round 5
// speedup vs baseline: 2.5710x; 1.5628x over previous
#include <cuda_runtime.h>
#include <cstdint>
#include <math.h>

#define T_STEPS 1000
#define I_DIM   100
#define H_DIM   5000
#define H4      (H_DIM/4)          // 1250 float4 per row
#define O_DIM   100
#define ALPHA_F 0.1f
#define NOISE_F 0.1f

#define NBLK   148       // persistent grid: one CTA per SM
#define NTH    512
#define NWARP  (NTH/32)
#define MAXR   34        // max rows per CTA

#define NC       10      // column chunks per step (5000 = 10 * 500)
#define CW       500     // floats per row per chunk
#define CW4      125     // float4 per row per chunk
#define STAGES   3
#define STAGE_F4 (MAXR * CW4)                 // 4250 float4 = 68000 B
#define DYN_BYTES ((STAGES*STAGE_F4 + H4) * 16 + 256)   // ~224.2 KB

__device__ float    g_inj[(size_t)T_STEPS * H_DIM];
__device__ unsigned g_bar;

__global__ void reset_k() { g_bar = 0u; }
__global__ void nop_k() {}

// ---------------------------------------------------------------------------
// inj[t][h] = sum_i u[t][i] * W_in[h][i] + 0.1 * noise[t][h]
// ---------------------------------------------------------------------------
__global__ void inj_k(const float* __restrict__ u,
                      const float* __restrict__ noise,
                      const float* __restrict__ W_in) {
    __shared__ float u_s[I_DIM];
    const int t   = blockIdx.y;
    const int tid = threadIdx.x;
    if (tid < I_DIM) u_s[tid] = u[(size_t)t * I_DIM + tid];
    __syncthreads();

    const int h = blockIdx.x * blockDim.x + tid;
    if (h < H_DIM) {
        const float4* w4 = reinterpret_cast<const float4*>(W_in + (size_t)h * I_DIM);
        float acc = 0.0f;
#pragma unroll
        for (int i = 0; i < I_DIM / 4; i++) {
            float4 w = __ldg(&w4[i]);
            acc = fmaf(w.x, u_s[4*i+0], acc);
            acc = fmaf(w.y, u_s[4*i+1], acc);
            acc = fmaf(w.z, u_s[4*i+2], acc);
            acc = fmaf(w.w, u_s[4*i+3], acc);
        }
        g_inj[(size_t)t * H_DIM + h] = acc + NOISE_F * noise[(size_t)t * H_DIM + h];
    }
}

// ---------------------------------------------------------------------------
// Persistent scan: cp.async 3-stage pipeline streaming W through smem.
// The stage ring index persists across steps (10 % 3 != 0, so the
// chunk->stage mapping drifts by one stage per step; tracking it with a
// rolling counter keeps producer and consumer aligned by construction).
// ---------------------------------------------------------------------------
__device__ __forceinline__ void cp16(unsigned int daddr, const float4* src) {
    asm volatile("cp.async.cg.shared.global [%0], [%1], 16;"
                 :: "r"(daddr), "l"(src));
}

__global__ void __launch_bounds__(NTH, 1)
scan_k(const float* __restrict__ W,
       const float* __restrict__ r_in,
       float* __restrict__ hs) {
    extern __shared__ float4 dyn4[];
    float4* wbuf = dyn4;                       // [STAGES][MAXR][CW4]
    float4* r4   = dyn4 + STAGES * STAGE_F4;   // 1250 float4 (20 KB)
    float*  x_s  = (float*)(r4 + H4);          // per-row membrane state

    const int tid  = threadIdx.x;
    const int bid  = blockIdx.x;
    const int wid  = tid >> 5;
    const int lane = tid & 31;

    const int row0  = (int)(((long long)bid     * H_DIM) / NBLK);
    const int row1  = (int)(((long long)(bid+1) * H_DIM) / NBLK);
    const int nrows = row1 - row0;             // 33 or 34

    if (tid < nrows) {
        float rv = r_in[row0 + tid];
        hs[row0 + tid] = rv;                   // hidden_states[0]
        x_s[tid] = atanhf(rv);
    }
    __syncthreads();

    const float4* W4 = reinterpret_cast<const float4*>(W);   // row stride 1250
    const int nldg = nrows * CW4;

    // Issue global column chunk c into smem stage s.
    auto issue = [&](int c, int s) {
        float4* dst = wbuf + s * STAGE_F4;
        for (int idx = tid; idx < nldg; idx += NTH) {
            const int rr = idx / CW4;
            const int cc = idx - rr * CW4;
            const float4* src = W4 + (size_t)(row0 + rr) * H4 + c * CW4 + cc;
            cp16((unsigned int)__cvta_generic_to_shared(dst + rr * CW4 + cc), src);
        }
        asm volatile("cp.async.commit_group;" ::: "memory");
    };

    issue(0, 0); issue(1, 1); issue(2, 2);     // prologue: fill pipeline
    int ring = 0;                              // stage of next chunk to consume

    for (int t = 0; t < T_STEPS; t++) {
        // Stage r_t into shared.
        const float4* rsrc = (t == 0)
            ? reinterpret_cast<const float4*>(r_in)
            : reinterpret_cast<const float4*>(hs + (size_t)t * H_DIM);
        for (int i = tid; i < H4; i += NTH) r4[i] = __ldcg(rsrc + i);

        float4 acc[3];
#pragma unroll
        for (int s = 0; s < 3; s++) acc[s] = make_float4(0.f, 0.f, 0.f, 0.f);
        __syncthreads();

        for (int c = 0; c < NC; c++) {
            asm volatile("cp.async.wait_group 2;" ::: "memory");
            __syncthreads();                   // chunk c resident for all warps

            const float4* wb = wbuf + ring * STAGE_F4;
            const float4* rc = r4 + c * CW4;
#pragma unroll
            for (int sub = 0; sub < 3; sub++) {
                const int lr = wid + sub * NWARP;
                if (lr < nrows) {
                    const float4* wrow = wb + lr * CW4;
                    float4 a = acc[sub];
#pragma unroll
                    for (int col = lane; col < CW4; col += 32) {
                        float4 w  = wrow[col];
                        float4 rv = rc[col];
                        a.x = fmaf(w.x, rv.x, a.x);
                        a.y = fmaf(w.y, rv.y, a.y);
                        a.z = fmaf(w.z, rv.z, a.z);
                        a.w = fmaf(w.w, rv.w, a.w);
                    }
                    acc[sub] = a;
                }
            }
            __syncthreads();                   // all warps done with this stage
            issue((c + 3) % NC, ring);         // refill freed stage (next data)
            ring = (ring + 1) % STAGES;
        }

        // Reduce + state update.
#pragma unroll
        for (int sub = 0; sub < 3; sub++) {
            const int lr = wid + sub * NWARP;
            if (lr < nrows) {
                float4 a = acc[sub];
                float s = (a.x + a.y) + (a.z + a.w);
                s += __shfl_down_sync(0xffffffffu, s, 16);
                s += __shfl_down_sync(0xffffffffu, s, 8);
                s += __shfl_down_sync(0xffffffffu, s, 4);
                s += __shfl_down_sync(0xffffffffu, s, 2);
                s += __shfl_down_sync(0xffffffffu, s, 1);
                if (lane == 0) {
                    const int row = row0 + lr;
                    const float injv = __ldcg(&g_inj[(size_t)t * H_DIM + row]);
                    float x = (1.0f - ALPHA_F) * x_s[lr] + ALPHA_F * (s + injv);
                    x_s[lr] = x;
                    hs[(size_t)(t + 1) * H_DIM + row] = tanhf(x);
                }
            }
        }
        if (lane == 0) __threadfence();        // release writers' stores
        __syncthreads();

        // Grid barrier: atomic arrive + read-only poll.
        if (tid == 0) {
            atomicAdd(&g_bar, 1u);
            const unsigned target = (unsigned)(t + 1) * (unsigned)NBLK;
            while (*((volatile unsigned*)&g_bar) < target) { }
            __threadfence();                   // acquire
        }
        __syncthreads();
    }

    asm volatile("cp.async.wait_group 0;" ::: "memory");
    __syncthreads();
}

// ---------------------------------------------------------------------------
// o[t][j] = sum_h hs[t+1][h] * W_out[j][h]
// ---------------------------------------------------------------------------
__global__ void out_k(const float* __restrict__ hs,
                      const float* __restrict__ W_out,
                      float* __restrict__ o) {
    __shared__ float r_s[H_DIM];
    const int t    = blockIdx.x;
    const int tid  = threadIdx.x;
    const int wid  = tid >> 5;
    const int lane = tid & 31;

    const float* r = hs + (size_t)(t + 1) * H_DIM;
    for (int c = tid; c < H_DIM; c += blockDim.x) r_s[c] = r[c];
    __syncthreads();

    for (int j = wid; j < O_DIM; j += blockDim.x / 32) {
        const float* wrow = W_out + (size_t)j * H_DIM;
        float acc = 0.0f;
        for (int c = lane; c < H_DIM; c += 32)
            acc = fmaf(__ldg(wrow + c), r_s[c], acc);
#pragma unroll
        for (int s = 16; s; s >>= 1) acc += __shfl_down_sync(0xffffffffu, acc, s);
        if (lane == 0) o[(size_t)t * O_DIM + j] = acc;
    }
}

// ---------------------------------------------------------------------------
// Inputs: u (T,I), r (H), noise (T,H), W_in (H,I), W_rec (H,H), W_out (O,H).
// Output: hidden_states (T+1,H) then o (T,O), fp32.
// ---------------------------------------------------------------------------
extern "C" void kernel_launch(void* const* d_in, const int* in_sizes, int n_in,
                              void* d_out, int out_size) {
    const float* u     = (const float*)d_in[0];
    const float* r     = (const float*)d_in[1];
    const float* noise = (const float*)d_in[2];
    const float* W_in  = (const float*)d_in[3];
    const float* W_rec = (const float*)d_in[4];
    const float* W_out = (const float*)d_in[5];

    float* hs = (float*)d_out;                       // (T+1, H)
    float* o  = hs + (size_t)(T_STEPS + 1) * H_DIM;  // (T, O)

    cudaFuncSetAttribute(scan_k, cudaFuncAttributeMaxDynamicSharedMemorySize,
                         DYN_BYTES);

    reset_k<<<1, 1>>>();
    dim3 gi((H_DIM + 255) / 256, T_STEPS);
    inj_k<<<gi, 256>>>(u, noise, W_in);
    nop_k<<<1, 1>>>();   // keeps scan_k on the ncu capture slot
    scan_k<<<NBLK, NTH, DYN_BYTES>>>(W_rec, r, hs);
    out_k<<<T_STEPS, 256>>>(hs, W_out, o);
}

// round 6
// speedup vs baseline: 3.2062x; 1.2471x over previous
#include <cuda_runtime.h>
#include <cstdint>
#include <math.h>

#define T_STEPS 1000
#define I_DIM   100
#define H_DIM   5000
#define H4      (H_DIM/4)          // 1250 float4 per row
#define O_DIM   100
#define ALPHA_F 0.1f
#define NOISE_F 0.1f

#define NBLK   148       // persistent grid: one CTA per SM
#define NTH    512
#define NWARP  (NTH/32)
#define MAXR   34        // max rows per CTA

#define NC       10      // column chunks per step (5000 = 10 * 500)
#define CW4      125     // float4 per row per chunk
#define STAGES   3
#define STAGE_F4 (MAXR * CW4)                 // 4250 float4 = 68000 B
#define DYN_BYTES ((STAGES*STAGE_F4 + H4) * 16 + 256)   // ~224.2 KB

__device__ float    g_inj[(size_t)T_STEPS * H_DIM];
__device__ unsigned g_bar;

__global__ void reset_k() { g_bar = 0u; }
__global__ void nop_k() {}

// ---------------------------------------------------------------------------
// inj[t][h] = sum_i u[t][i] * W_in[h][i] + 0.1 * noise[t][h]
// ---------------------------------------------------------------------------
__global__ void inj_k(const float* __restrict__ u,
                      const float* __restrict__ noise,
                      const float* __restrict__ W_in) {
    __shared__ float u_s[I_DIM];
    const int t   = blockIdx.y;
    const int tid = threadIdx.x;
    if (tid < I_DIM) u_s[tid] = u[(size_t)t * I_DIM + tid];
    __syncthreads();

    const int h = blockIdx.x * blockDim.x + tid;
    if (h < H_DIM) {
        const float4* w4 = reinterpret_cast<const float4*>(W_in + (size_t)h * I_DIM);
        float acc = 0.0f;
#pragma unroll
        for (int i = 0; i < I_DIM / 4; i++) {
            float4 w = __ldg(&w4[i]);
            acc = fmaf(w.x, u_s[4*i+0], acc);
            acc = fmaf(w.y, u_s[4*i+1], acc);
            acc = fmaf(w.z, u_s[4*i+2], acc);
            acc = fmaf(w.w, u_s[4*i+3], acc);
        }
        g_inj[(size_t)t * H_DIM + h] = acc + NOISE_F * noise[(size_t)t * H_DIM + h];
    }
}

// ---------------------------------------------------------------------------
// Persistent scan. Pipeline invariant: global chunk counter k = t*NC + c
// lives in stage k % 3. At iteration k we: wait chunk k, sync (frees stage
// of k-1), issue global chunk k+2 into stage (k+2)%3 (== stage of k-1),
// then compute chunk k. One __syncthreads per chunk.
// ---------------------------------------------------------------------------
__device__ __forceinline__ void cp16(unsigned int daddr, const float4* src) {
    asm volatile("cp.async.cg.shared.global [%0], [%1], 16;"
                 :: "r"(daddr), "l"(src));
}

__global__ void __launch_bounds__(NTH, 1)
scan_k(const float* __restrict__ W,
       const float* __restrict__ r_in,
       float* __restrict__ hs) {
    extern __shared__ float4 dyn4[];
    float4* wbuf = dyn4;                       // [STAGES][MAXR][CW4]
    float4* r4   = dyn4 + STAGES * STAGE_F4;   // 1250 float4 (20 KB)
    float*  x_s  = (float*)(r4 + H4);          // per-row membrane state

    const int tid  = threadIdx.x;
    const int bid  = blockIdx.x;
    const int wid  = tid >> 5;
    const int lane = tid & 31;

    const int row0  = (int)(((long long)bid     * H_DIM) / NBLK);
    const int row1  = (int)(((long long)(bid+1) * H_DIM) / NBLK);
    const int nrows = row1 - row0;             // 33 or 34

    // Warp's three local rows (lr2 may be out of range).
    const int lr0 = wid;
    const int lr1 = wid + NWARP;
    const int lr2 = wid + 2 * NWARP;
    const bool has2 = (lr2 < nrows);           // lr0, lr1 always < 33

    if (tid < nrows) {
        float rv = r_in[row0 + tid];
        hs[row0 + tid] = rv;                   // hidden_states[0]
        x_s[tid] = atanhf(rv);
    }
    __syncthreads();

    const float4* W4 = reinterpret_cast<const float4*>(W);   // row stride 1250

    // Division-free issue of data chunk c into stage s.
    // Warp w copies rows {w, w+16, w+32}; lane covers cols {l,l+32,l+64,l+96}.
    auto issue = [&](int c, int s) {
        float4* dstbase = wbuf + s * STAGE_F4;
#pragma unroll
        for (int sub = 0; sub < 3; sub++) {
            const int lr = wid + sub * NWARP;
            if (sub < 2 || lr < nrows) {
                const float4* src = W4 + (size_t)(row0 + lr) * H4 + c * CW4 + lane;
                float4* dst = dstbase + lr * CW4 + lane;
#pragma unroll
                for (int it = 0; it < 4; it++) {
                    if (it < 3 || lane < CW4 - 96)
                        cp16((unsigned int)__cvta_generic_to_shared(dst + it * 32),
                             src + it * 32);
                }
            }
        }
        asm volatile("cp.async.commit_group;" ::: "memory");
    };

    issue(0, 0); issue(1, 1);                  // prologue: k=0,1
    int stage = 0;                             // k % 3, carried across steps
    int nstage = 2;                            // (k+2) % 3
    int nchunk = 2;                            // (k+2) % NC

    for (int t = 0; t < T_STEPS; t++) {
        // Stage r_t into shared (visibility covered by the c=0 sync below).
        const float4* rsrc = (t == 0)
            ? reinterpret_cast<const float4*>(r_in)
            : reinterpret_cast<const float4*>(hs + (size_t)t * H_DIM);
        for (int i = tid; i < H4; i += NTH) r4[i] = __ldcg(rsrc + i);

        float4 a0 = make_float4(0.f,0.f,0.f,0.f);
        float4 a1 = make_float4(0.f,0.f,0.f,0.f);
        float4 a2 = make_float4(0.f,0.f,0.f,0.f);

        for (int c = 0; c < NC; c++) {
            asm volatile("cp.async.wait_group 1;" ::: "memory");
            __syncthreads();                   // chunk k resident; stage of k-1 free

            issue(nchunk, nstage);             // refill freed stage
            nstage = (nstage == 2) ? 0 : nstage + 1;
            nchunk = (nchunk == NC - 1) ? 0 : nchunk + 1;

            const float4* wb = wbuf + stage * STAGE_F4;
            stage = (stage == 2) ? 0 : stage + 1;
            const float4* rc = r4 + c * CW4;
            const float4* w0 = wb + lr0 * CW4;
            const float4* w1 = wb + lr1 * CW4;
            const float4* w2 = wb + lr2 * CW4;

#pragma unroll
            for (int it = 0; it < 4; it++) {
                const int col = lane + it * 32;
                if (it < 3 || lane < CW4 - 96) {
                    const float4 rv = rc[col];
                    {   const float4 w = w0[col];
                        a0.x = fmaf(w.x, rv.x, a0.x); a0.y = fmaf(w.y, rv.y, a0.y);
                        a0.z = fmaf(w.z, rv.z, a0.z); a0.w = fmaf(w.w, rv.w, a0.w); }
                    {   const float4 w = w1[col];
                        a1.x = fmaf(w.x, rv.x, a1.x); a1.y = fmaf(w.y, rv.y, a1.y);
                        a1.z = fmaf(w.z, rv.z, a1.z); a1.w = fmaf(w.w, rv.w, a1.w); }
                    if (has2) {
                        const float4 w = w2[col];
                        a2.x = fmaf(w.x, rv.x, a2.x); a2.y = fmaf(w.y, rv.y, a2.y);
                        a2.z = fmaf(w.z, rv.z, a2.z); a2.w = fmaf(w.w, rv.w, a2.w); }
                }
            }
        }

        // Reduce + state update for the warp's rows.
        float s0 = (a0.x + a0.y) + (a0.z + a0.w);
        float s1 = (a1.x + a1.y) + (a1.z + a1.w);
        float s2 = (a2.x + a2.y) + (a2.z + a2.w);
#pragma unroll
        for (int sh = 16; sh; sh >>= 1) {
            s0 += __shfl_down_sync(0xffffffffu, s0, sh);
            s1 += __shfl_down_sync(0xffffffffu, s1, sh);
            s2 += __shfl_down_sync(0xffffffffu, s2, sh);
        }
        if (lane == 0) {
            {   const int row = row0 + lr0;
                float x = (1.0f-ALPHA_F)*x_s[lr0]
                        + ALPHA_F*(s0 + __ldcg(&g_inj[(size_t)t*H_DIM + row]));
                x_s[lr0] = x;
                hs[(size_t)(t+1)*H_DIM + row] = tanhf(x); }
            {   const int row = row0 + lr1;
                float x = (1.0f-ALPHA_F)*x_s[lr1]
                        + ALPHA_F*(s1 + __ldcg(&g_inj[(size_t)t*H_DIM + row]));
                x_s[lr1] = x;
                hs[(size_t)(t+1)*H_DIM + row] = tanhf(x); }
            if (has2) {
                const int row = row0 + lr2;
                float x = (1.0f-ALPHA_F)*x_s[lr2]
                        + ALPHA_F*(s2 + __ldcg(&g_inj[(size_t)t*H_DIM + row]));
                x_s[lr2] = x;
                hs[(size_t)(t+1)*H_DIM + row] = tanhf(x); }
            __threadfence();                   // release this warp's stores
        }
        __syncthreads();

        // Grid barrier: atomic arrive + read-only poll.
        if (tid == 0) {
            atomicAdd(&g_bar, 1u);
            const unsigned target = (unsigned)(t + 1) * (unsigned)NBLK;
            while (*((volatile unsigned*)&g_bar) < target) { }
            __threadfence();                   // acquire
        }
        __syncthreads();
    }

    asm volatile("cp.async.wait_group 0;" ::: "memory");
    __syncthreads();
}

// ---------------------------------------------------------------------------
// o[t][j] = sum_h hs[t+1][h] * W_out[j][h]
// ---------------------------------------------------------------------------
__global__ void out_k(const float* __restrict__ hs,
                      const float* __restrict__ W_out,
                      float* __restrict__ o) {
    __shared__ float r_s[H_DIM];
    const int t    = blockIdx.x;
    const int tid  = threadIdx.x;
    const int wid  = tid >> 5;
    const int lane = tid & 31;

    const float* r = hs + (size_t)(t + 1) * H_DIM;
    for (int c = tid; c < H_DIM; c += blockDim.x) r_s[c] = r[c];
    __syncthreads();

    for (int j = wid; j < O_DIM; j += blockDim.x / 32) {
        const float* wrow = W_out + (size_t)j * H_DIM;
        float acc = 0.0f;
        for (int c = lane; c < H_DIM; c += 32)
            acc = fmaf(__ldg(wrow + c), r_s[c], acc);
#pragma unroll
        for (int s = 16; s; s >>= 1) acc += __shfl_down_sync(0xffffffffu, acc, s);
        if (lane == 0) o[(size_t)t * O_DIM + j] = acc;
    }
}

// ---------------------------------------------------------------------------
// Inputs: u (T,I), r (H), noise (T,H), W_in (H,I), W_rec (H,H), W_out (O,H).
// Output: hidden_states (T+1,H) then o (T,O), fp32.
// ---------------------------------------------------------------------------
extern "C" void kernel_launch(void* const* d_in, const int* in_sizes, int n_in,
                              void* d_out, int out_size) {
    const float* u     = (const float*)d_in[0];
    const float* r     = (const float*)d_in[1];
    const float* noise = (const float*)d_in[2];
    const float* W_in  = (const float*)d_in[3];
    const float* W_rec = (const float*)d_in[4];
    const float* W_out = (const float*)d_in[5];

    float* hs = (float*)d_out;                       // (T+1, H)
    float* o  = hs + (size_t)(T_STEPS + 1) * H_DIM;  // (T, O)

    cudaFuncSetAttribute(scan_k, cudaFuncAttributeMaxDynamicSharedMemorySize,
                         DYN_BYTES);

    reset_k<<<1, 1>>>();
    dim3 gi((H_DIM + 255) / 256, T_STEPS);
    inj_k<<<gi, 256>>>(u, noise, W_in);
    nop_k<<<1, 1>>>();   // keeps scan_k on the ncu capture slot
    scan_k<<<NBLK, NTH, DYN_BYTES>>>(W_rec, r, hs);
    out_k<<<T_STEPS, 256>>>(hs, W_out, o);
}

// round 7
// speedup vs baseline: 4.1407x; 1.2915x over previous
#include <cuda_runtime.h>
#include <cuda_fp16.h>
#include <cstdint>
#include <math.h>

#define T_STEPS 1000
#define I_DIM   100
#define H_DIM   5000
#define H4      (H_DIM/4)            // 1250 float4 per fp32 row
#define O_DIM   100
#define ALPHA_F 0.1f
#define NOISE_F 0.1f

#define NBLK   148       // persistent grid: one CTA per SM
#define NTH    512
#define NWARP  (NTH/32)
#define MAXR   34        // max rows per CTA

#define NC       5       // column chunks per step (5000 = 5 * 1000)
#define CU4      125     // uint4 (8 halves) per row per chunk
#define HROW_U4  625     // uint4 per fp16 W row (5000 halves = 10000 B)
#define STAGES   3
#define STAGE_U4 (MAXR * CU4)                  // 4250 uint4 = 68000 B
#define DYN_BYTES (STAGES*STAGE_U4*16 + H4*16 + 256)    // ~224.2 KB

#define N_WU4  ((size_t)H_DIM * H_DIM / 8)     // 3,125,000 uint4

__device__ float    g_inj[(size_t)T_STEPS * H_DIM];
__device__ uint4    g_wh4[N_WU4];              // W_rec in fp16, row-major
__device__ unsigned g_bar;

__global__ void reset_k() { g_bar = 0u; }

// ---------------------------------------------------------------------------
// Convert W_rec fp32 -> fp16 (one pass; streaming reads keep L2 for g_wh4).
// ---------------------------------------------------------------------------
__global__ void cvt_k(const float* __restrict__ W) {
    const size_t i = (size_t)blockIdx.x * blockDim.x + threadIdx.x;
    if (i < N_WU4) {
        const float4* s = reinterpret_cast<const float4*>(W) + 2 * i;
        const float4 a = __ldcs(s);
        const float4 b = __ldcs(s + 1);
        uint4 o;
        __half2* p = reinterpret_cast<__half2*>(&o);
        p[0] = __floats2half2_rn(a.x, a.y);
        p[1] = __floats2half2_rn(a.z, a.w);
        p[2] = __floats2half2_rn(b.x, b.y);
        p[3] = __floats2half2_rn(b.z, b.w);
        g_wh4[i] = o;
    }
}

// ---------------------------------------------------------------------------
// inj[t][h] = sum_i u[t][i] * W_in[h][i] + 0.1 * noise[t][h]
// ---------------------------------------------------------------------------
__global__ void inj_k(const float* __restrict__ u,
                      const float* __restrict__ noise,
                      const float* __restrict__ W_in) {
    __shared__ float u_s[I_DIM];
    const int t   = blockIdx.y;
    const int tid = threadIdx.x;
    if (tid < I_DIM) u_s[tid] = u[(size_t)t * I_DIM + tid];
    __syncthreads();

    const int h = blockIdx.x * blockDim.x + tid;
    if (h < H_DIM) {
        const float4* w4 = reinterpret_cast<const float4*>(W_in + (size_t)h * I_DIM);
        float acc = 0.0f;
#pragma unroll
        for (int i = 0; i < I_DIM / 4; i++) {
            float4 w = __ldg(&w4[i]);
            acc = fmaf(w.x, u_s[4*i+0], acc);
            acc = fmaf(w.y, u_s[4*i+1], acc);
            acc = fmaf(w.z, u_s[4*i+2], acc);
            acc = fmaf(w.w, u_s[4*i+3], acc);
        }
        g_inj[(size_t)t * H_DIM + h] = acc + NOISE_F * noise[(size_t)t * H_DIM + h];
    }
}

// ---------------------------------------------------------------------------
// Persistent scan, fp16 weight stream. Pipeline invariant: global chunk
// counter k = t*NC + c lives in stage k % 3; wait chunk k, sync (frees
// stage of k-1), issue chunk k+2 into stage (k+2)%3, compute chunk k.
// ---------------------------------------------------------------------------
__device__ __forceinline__ void cp16(unsigned int daddr, const uint4* src) {
    asm volatile("cp.async.cg.shared.global [%0], [%1], 16;"
                 :: "r"(daddr), "l"(src));
}

__device__ __forceinline__ void fma8(float4& a, const uint4 wv,
                                     const float4 rA, const float4 rB) {
    const __half2* h = reinterpret_cast<const __half2*>(&wv);
    const float2 f0 = __half22float2(h[0]);
    const float2 f1 = __half22float2(h[1]);
    const float2 f2 = __half22float2(h[2]);
    const float2 f3 = __half22float2(h[3]);
    a.x = fmaf(f0.x, rA.x, a.x); a.y = fmaf(f0.y, rA.y, a.y);
    a.z = fmaf(f1.x, rA.z, a.z); a.w = fmaf(f1.y, rA.w, a.w);
    a.x = fmaf(f2.x, rB.x, a.x); a.y = fmaf(f2.y, rB.y, a.y);
    a.z = fmaf(f3.x, rB.z, a.z); a.w = fmaf(f3.y, rB.w, a.w);
}

__global__ void __launch_bounds__(NTH, 1)
scan_k(const float* __restrict__ r_in,
       float* __restrict__ hs) {
    extern __shared__ uint4 dynu[];
    uint4*  wbuf = dynu;                        // [STAGES][MAXR][CU4]
    float4* r4   = reinterpret_cast<float4*>(dynu + STAGES * STAGE_U4);  // 1250
    float*  x_s  = reinterpret_cast<float*>(r4 + H4);

    const int tid  = threadIdx.x;
    const int bid  = blockIdx.x;
    const int wid  = tid >> 5;
    const int lane = tid & 31;

    const int row0  = (int)(((long long)bid     * H_DIM) / NBLK);
    const int row1  = (int)(((long long)(bid+1) * H_DIM) / NBLK);
    const int nrows = row1 - row0;              // 33 or 34

    const int lr0 = wid;
    const int lr1 = wid + NWARP;
    const int lr2 = wid + 2 * NWARP;
    const bool has2 = (lr2 < nrows);

    if (tid < nrows) {
        float rv = r_in[row0 + tid];
        hs[row0 + tid] = rv;                    // hidden_states[0]
        x_s[tid] = atanhf(rv);
    }
    __syncthreads();

    // Issue data chunk c into stage s (division-free, warp-per-row).
    auto issue = [&](int c, int s) {
        uint4* dstbase = wbuf + s * STAGE_U4;
#pragma unroll
        for (int sub = 0; sub < 3; sub++) {
            const int lr = wid + sub * NWARP;
            if (sub < 2 || lr < nrows) {
                const uint4* src = g_wh4 + (size_t)(row0 + lr) * HROW_U4
                                 + c * CU4 + lane;
                uint4* dst = dstbase + lr * CU4 + lane;
#pragma unroll
                for (int it = 0; it < 4; it++) {
                    if (it < 3 || lane < CU4 - 96)
                        cp16((unsigned int)__cvta_generic_to_shared(dst + it * 32),
                             src + it * 32);
                }
            }
        }
        asm volatile("cp.async.commit_group;" ::: "memory");
    };

    issue(0, 0); issue(1, 1);                   // prologue: k=0,1
    int stage = 0;                              // k % 3, carried across steps
    int nstage = 2;                             // (k+2) % 3
    int nchunk = 2;                             // (k+2) % NC

    for (int t = 0; t < T_STEPS; t++) {
        // Stage r_t into shared (visibility covered by the c=0 sync below).
        const float4* rsrc = (t == 0)
            ? reinterpret_cast<const float4*>(r_in)
            : reinterpret_cast<const float4*>(hs + (size_t)t * H_DIM);
        for (int i = tid; i < H4; i += NTH) r4[i] = __ldcg(rsrc + i);

        float4 a0 = make_float4(0.f,0.f,0.f,0.f);
        float4 a1 = make_float4(0.f,0.f,0.f,0.f);
        float4 a2 = make_float4(0.f,0.f,0.f,0.f);

        for (int c = 0; c < NC; c++) {
            asm volatile("cp.async.wait_group 1;" ::: "memory");
            __syncthreads();                    // chunk k resident; k-1 stage free

            issue(nchunk, nstage);              // refill freed stage
            nstage = (nstage == 2) ? 0 : nstage + 1;
            nchunk = (nchunk == NC - 1) ? 0 : nchunk + 1;

            const uint4* wb = wbuf + stage * STAGE_U4;
            stage = (stage == 2) ? 0 : stage + 1;
            const float4* rc = r4 + c * (CU4 * 2);      // 250 float4 per chunk
            const uint4* w0 = wb + lr0 * CU4;
            const uint4* w1 = wb + lr1 * CU4;
            const uint4* w2 = wb + lr2 * CU4;

#pragma unroll
            for (int it = 0; it < 4; it++) {
                const int col = lane + it * 32;
                if (it < 3 || lane < CU4 - 96) {
                    const float4 rA = rc[2*col];
                    const float4 rB = rc[2*col + 1];
                    fma8(a0, w0[col], rA, rB);
                    fma8(a1, w1[col], rA, rB);
                    if (has2) fma8(a2, w2[col], rA, rB);
                }
            }
        }

        // Reduce + state update for the warp's rows.
        float s0 = (a0.x + a0.y) + (a0.z + a0.w);
        float s1 = (a1.x + a1.y) + (a1.z + a1.w);
        float s2 = (a2.x + a2.y) + (a2.z + a2.w);
#pragma unroll
        for (int sh = 16; sh; sh >>= 1) {
            s0 += __shfl_down_sync(0xffffffffu, s0, sh);
            s1 += __shfl_down_sync(0xffffffffu, s1, sh);
            s2 += __shfl_down_sync(0xffffffffu, s2, sh);
        }
        if (lane == 0) {
            {   const int row = row0 + lr0;
                float x = (1.0f-ALPHA_F)*x_s[lr0]
                        + ALPHA_F*(s0 + __ldcg(&g_inj[(size_t)t*H_DIM + row]));
                x_s[lr0] = x;
                hs[(size_t)(t+1)*H_DIM + row] = tanhf(x); }
            {   const int row = row0 + lr1;
                float x = (1.0f-ALPHA_F)*x_s[lr1]
                        + ALPHA_F*(s1 + __ldcg(&g_inj[(size_t)t*H_DIM + row]));
                x_s[lr1] = x;
                hs[(size_t)(t+1)*H_DIM + row] = tanhf(x); }
            if (has2) {
                const int row = row0 + lr2;
                float x = (1.0f-ALPHA_F)*x_s[lr2]
                        + ALPHA_F*(s2 + __ldcg(&g_inj[(size_t)t*H_DIM + row]));
                x_s[lr2] = x;
                hs[(size_t)(t+1)*H_DIM + row] = tanhf(x); }
            __threadfence();                    // release this warp's stores
        }
        __syncthreads();

        // Grid barrier: atomic arrive + read-only poll.
        if (tid == 0) {
            atomicAdd(&g_bar, 1u);
            const unsigned target = (unsigned)(t + 1) * (unsigned)NBLK;
            while (*((volatile unsigned*)&g_bar) < target) { }
            __threadfence();                    // acquire
        }
        __syncthreads();
    }

    asm volatile("cp.async.wait_group 0;" ::: "memory");
    __syncthreads();
}

// ---------------------------------------------------------------------------
// o[t][j] = sum_h hs[t+1][h] * W_out[j][h]
// ---------------------------------------------------------------------------
__global__ void out_k(const float* __restrict__ hs,
                      const float* __restrict__ W_out,
                      float* __restrict__ o) {
    __shared__ float r_s[H_DIM];
    const int t    = blockIdx.x;
    const int tid  = threadIdx.x;
    const int wid  = tid >> 5;
    const int lane = tid & 31;

    const float* r = hs + (size_t)(t + 1) * H_DIM;
    for (int c = tid; c < H_DIM; c += blockDim.x) r_s[c] = r[c];
    __syncthreads();

    for (int j = wid; j < O_DIM; j += blockDim.x / 32) {
        const float* wrow = W_out + (size_t)j * H_DIM;
        float acc = 0.0f;
        for (int c = lane; c < H_DIM; c += 32)
            acc = fmaf(__ldg(wrow + c), r_s[c], acc);
#pragma unroll
        for (int s = 16; s; s >>= 1) acc += __shfl_down_sync(0xffffffffu, acc, s);
        if (lane == 0) o[(size_t)t * O_DIM + j] = acc;
    }
}

// ---------------------------------------------------------------------------
// Inputs: u (T,I), r (H), noise (T,H), W_in (H,I), W_rec (H,H), W_out (O,H).
// Output: hidden_states (T+1,H) then o (T,O), fp32.
// ---------------------------------------------------------------------------
extern "C" void kernel_launch(void* const* d_in, const int* in_sizes, int n_in,
                              void* d_out, int out_size) {
    const float* u     = (const float*)d_in[0];
    const float* r     = (const float*)d_in[1];
    const float* noise = (const float*)d_in[2];
    const float* W_in  = (const float*)d_in[3];
    const float* W_rec = (const float*)d_in[4];
    const float* W_out = (const float*)d_in[5];

    float* hs = (float*)d_out;                       // (T+1, H)
    float* o  = hs + (size_t)(T_STEPS + 1) * H_DIM;  // (T, O)

    cudaFuncSetAttribute(scan_k, cudaFuncAttributeMaxDynamicSharedMemorySize,
                         DYN_BYTES);

    reset_k<<<1, 1>>>();
    dim3 gi((H_DIM + 255) / 256, T_STEPS);
    inj_k<<<gi, 256>>>(u, noise, W_in);
    cvt_k<<<(int)((N_WU4 + 255) / 256), 256>>>(W_rec);
    scan_k<<<NBLK, NTH, DYN_BYTES>>>(r, hs);
    out_k<<<T_STEPS, 256>>>(hs, W_out, o);
}